// round 16
// baseline (speedup 1.0000x reference)
#include <cuda_runtime.h>

// ObservabilityWeightedMSE — weighted-MSE reduction, two launches with PDL.
// d_in[0]=predictions [500000,82] f32, d_in[1]=targets [500000,82] f32,
// d_in[2]=inputs [500000,400] f32. Output: scalar f32.
//
// Locked-in: two-launch family; per-block atomicAdd(double); <<<1,1>>>
// finalize; launch_bounds(256,8); gather-style inputs load; 8-wave grid
// (wave sweep: 1->163.2, 4->159.9, 8->158.2, 16->158.2).
// R16: finalize launched with Programmatic Stream Serialization (PDL) so its
//      launch overhead overlaps the main kernel; griddepcontrol.wait inside
//      finalize provides the completion + memory-visibility barrier.

#define THRESH   1e-4f
#define NCOLS    82
#define ROW_IN   400
#define NBLOCKS  9472            // 8 waves at 8 blocks/SM x 148 SMs
#define NTHREADS 256

__device__ double g_acc = 0.0;   // reset by finalize after each use

__global__ void __launch_bounds__(NTHREADS, 8)   // cap regs at 32: 8 blocks/SM
wmse_kernel(const float* __restrict__ pred,
            const float* __restrict__ targ,
            const float* __restrict__ inp,
            int B)
{
    const int lane  = threadIdx.x & 31;
    const int warp  = threadIdx.x >> 5;
    const int gwarp = blockIdx.x * (NTHREADS / 32) + warp;
    const int nwarp = NBLOCKS * (NTHREADS / 32);

    // lane-constant geometry for the inputs magnitude slice
    const int  n0   = lane / 5, p0 = lane % 5;      // float4 idx = lane
    const int  i1   = 32 + lane;
    const int  n1   = i1 / 5,  p1 = i1 % 5;         // float4 idx = 32+lane
    const bool has1 = (i1 < 50);                    // lanes 0..17
    const int  off0 = n0 * 40 + p0 * 4;
    const int  off1 = n1 * 40 + p1 * 4;

    float acc = 0.0f;

    for (int r = gwarp; r < B; r += nwarp) {
        const float* pin = inp + (size_t)r * ROW_IN;

        // ---- node-below test: below[n] <=> max of 20 magnitudes < THRESH ----
        float4 a0 = *(const float4*)(pin + off0);
        unsigned ok = 0;
        if (fmaxf(fmaxf(a0.x, a0.y), fmaxf(a0.z, a0.w)) >= THRESH)
            ok = 1u << n0;
        if (has1) {
            float4 a1 = *(const float4*)(pin + off1);
            if (fmaxf(fmaxf(a1.x, a1.y), fmaxf(a1.z, a1.w)) >= THRESH)
                ok |= 1u << n1;
        }
        unsigned below = (~__reduce_or_sync(0xffffffffu, ok)) & 0x3FFu;
        // below==0 -> ffs(0x400)=11 -> cut=44 > max col 40 -> never cuts
        const int cut = __ffs(below | 0x400u) << 2;

        // ---- weighted MSE over 82 columns, coalesced scalar loads ----
        const float* pp = pred + (size_t)r * NCOLS;
        const float* pt = targ + (size_t)r * NCOLS;
        #pragma unroll
        for (int it = 0; it < 3; ++it) {
            int c = it * 32 + lane;
            if (c < NCOLS) {
                float d = pp[c] - pt[c];
                bool five; int col;
                if (c < 41) { col = c; five = ((c & 3) == 0); }
                else {
                    int j = c - 41; col = j;
                    five = ((j & 3) == 3) || (((j & 3) == 0) && (j != 40));
                }
                float w = five ? 5.0f : 1.0f;
                if (col >= cut) w *= 0.1f;
                acc = fmaf(d * d, w, acc);
            }
        }
    }

    // ---- block reduction -> one double atomic per block ----
    #pragma unroll
    for (int o = 16; o > 0; o >>= 1)
        acc += __shfl_down_sync(0xffffffffu, acc, o);

    __shared__ float smem[NTHREADS / 32];
    if (lane == 0) smem[warp] = acc;
    __syncthreads();
    if (warp == 0) {
        float v = (lane < (NTHREADS / 32)) ? smem[lane] : 0.0f;
        #pragma unroll
        for (int o = 4; o > 0; o >>= 1)
            v += __shfl_down_sync(0xffffffffu, v, o);
        if (lane == 0) atomicAdd(&g_acc, (double)v);
    }
}

// Finalize with PDL: pre-launched while wmse_kernel runs; griddepcontrol.wait
// returns only after the primary grid fully completes (implicit trigger —
// wmse_kernel never calls launch_dependents), guaranteeing all block atomics
// are visible. Then: read, scale, write, reset.
__global__ void finalize_kernel(float* __restrict__ out, double inv_total)
{
    asm volatile("griddepcontrol.wait;" ::: "memory");
    out[0] = (float)(g_acc * inv_total);
    g_acc  = 0.0;
}

extern "C" void kernel_launch(void* const* d_in, const int* in_sizes, int n_in,
                              void* d_out, int out_size)
{
    const float* pred = (const float*)d_in[0];
    const float* targ = (const float*)d_in[1];
    const float* inp  = (const float*)d_in[2];
    float* out = (float*)d_out;

    const int B = in_sizes[0] / NCOLS;   // 500000

    wmse_kernel<<<NBLOCKS, NTHREADS>>>(pred, targ, inp, B);

    // PDL launch of finalize: overlaps its launch latency with wmse_kernel.
    cudaLaunchConfig_t cfg = {};
    cfg.gridDim  = dim3(1, 1, 1);
    cfg.blockDim = dim3(1, 1, 1);
    cfg.dynamicSmemBytes = 0;
    cfg.stream = 0;
    cudaLaunchAttribute attr[1];
    attr[0].id = cudaLaunchAttributeProgrammaticStreamSerialization;
    attr[0].val.programmaticStreamSerializationAllowed = 1;
    cfg.attrs = attr;
    cfg.numAttrs = 1;
    double inv_total = 1.0 / ((double)B * NCOLS);
    cudaLaunchKernelEx(&cfg, finalize_kernel, out, inv_total);
}

// round 17
// speedup vs baseline: 1.0026x; 1.0026x over previous
#include <cuda_runtime.h>

// ObservabilityWeightedMSE — single compute kernel + 4-byte memset node.
// d_in[0]=predictions [500000,82] f32, d_in[1]=targets [500000,82] f32,
// d_in[2]=inputs [500000,400] f32. Output: scalar f32.
//
// Locked-in: launch_bounds(256,8); gather-style inputs load; 8-wave grid
// (sweep: 1->163.2, 4->159.9, 8->158.2, 16->158.2); relaxed per-block
// atomics are free (R10/R13), fused last-block tails cost +15us (R5/7/8),
// PDL neutral (R16), main kernel is at the ~150us traffic floor.
// R17: kill the finalize kernel entirely — blocks atomicAdd pre-scaled float
//      partials straight into d_out; a cudaMemsetAsync graph node zeroes the
//      poisoned output first. No last-block logic, no device globals.

#define THRESH   1e-4f
#define NCOLS    82
#define ROW_IN   400
#define NBLOCKS  9472            // 8 waves at 8 blocks/SM x 148 SMs
#define NTHREADS 256

__global__ void __launch_bounds__(NTHREADS, 8)   // cap regs at 32: 8 blocks/SM
wmse_kernel(const float* __restrict__ pred,
            const float* __restrict__ targ,
            const float* __restrict__ inp,
            int B, float inv_total, float* __restrict__ out)
{
    const int lane  = threadIdx.x & 31;
    const int warp  = threadIdx.x >> 5;
    const int gwarp = blockIdx.x * (NTHREADS / 32) + warp;
    const int nwarp = NBLOCKS * (NTHREADS / 32);

    // lane-constant geometry for the inputs magnitude slice
    const int  n0   = lane / 5, p0 = lane % 5;      // float4 idx = lane
    const int  i1   = 32 + lane;
    const int  n1   = i1 / 5,  p1 = i1 % 5;         // float4 idx = 32+lane
    const bool has1 = (i1 < 50);                    // lanes 0..17
    const int  off0 = n0 * 40 + p0 * 4;
    const int  off1 = n1 * 40 + p1 * 4;

    float acc = 0.0f;

    for (int r = gwarp; r < B; r += nwarp) {
        const float* pin = inp + (size_t)r * ROW_IN;

        // ---- node-below test: below[n] <=> max of 20 magnitudes < THRESH ----
        float4 a0 = *(const float4*)(pin + off0);
        unsigned ok = 0;
        if (fmaxf(fmaxf(a0.x, a0.y), fmaxf(a0.z, a0.w)) >= THRESH)
            ok = 1u << n0;
        if (has1) {
            float4 a1 = *(const float4*)(pin + off1);
            if (fmaxf(fmaxf(a1.x, a1.y), fmaxf(a1.z, a1.w)) >= THRESH)
                ok |= 1u << n1;
        }
        unsigned below = (~__reduce_or_sync(0xffffffffu, ok)) & 0x3FFu;
        // below==0 -> ffs(0x400)=11 -> cut=44 > max col 40 -> never cuts
        const int cut = __ffs(below | 0x400u) << 2;

        // ---- weighted MSE over 82 columns, coalesced scalar loads ----
        const float* pp = pred + (size_t)r * NCOLS;
        const float* pt = targ + (size_t)r * NCOLS;
        #pragma unroll
        for (int it = 0; it < 3; ++it) {
            int c = it * 32 + lane;
            if (c < NCOLS) {
                float d = pp[c] - pt[c];
                bool five; int col;
                if (c < 41) { col = c; five = ((c & 3) == 0); }
                else {
                    int j = c - 41; col = j;
                    five = ((j & 3) == 3) || (((j & 3) == 0) && (j != 40));
                }
                float w = five ? 5.0f : 1.0f;
                if (col >= cut) w *= 0.1f;
                acc = fmaf(d * d, w, acc);
            }
        }
    }

    // ---- block reduction -> one pre-scaled float atomic into d_out ----
    #pragma unroll
    for (int o = 16; o > 0; o >>= 1)
        acc += __shfl_down_sync(0xffffffffu, acc, o);

    __shared__ float smem[NTHREADS / 32];
    if (lane == 0) smem[warp] = acc;
    __syncthreads();
    if (warp == 0) {
        float v = (lane < (NTHREADS / 32)) ? smem[lane] : 0.0f;
        #pragma unroll
        for (int o = 4; o > 0; o >>= 1)
            v += __shfl_down_sync(0xffffffffu, v, o);
        if (lane == 0) atomicAdd(out, v * inv_total);
    }
}

extern "C" void kernel_launch(void* const* d_in, const int* in_sizes, int n_in,
                              void* d_out, int out_size)
{
    const float* pred = (const float*)d_in[0];
    const float* targ = (const float*)d_in[1];
    const float* inp  = (const float*)d_in[2];
    float* out = (float*)d_out;

    const int B = in_sizes[0] / NCOLS;   // 500000

    // zero the poisoned output (graph-capturable async memset node)
    cudaMemsetAsync(out, 0, sizeof(float));

    wmse_kernel<<<NBLOCKS, NTHREADS>>>(pred, targ, inp, B,
                                       (float)(1.0 / ((double)B * NCOLS)), out);
}